// round 5
// baseline (speedup 1.0000x reference)
#include <cuda_runtime.h>
#include <cuda_bf16.h>

// Mixed pooling, 2x2 stride-2, NHWC:
//   out[b,ho,wo,c] = (1-k)*max(window) + k*mean(window)
// x: [32,256,256,128] f32, k: [32,128,128,128] i32, out: [32,128,128,128] f32
//
// HBM-bound streaming kernel at ~91% of spec HBM; traffic minimal (1.61 GB).
// R5: persistent grid-stride — 148 SMs x 4 resident CTAs of 512 threads
// (full occupancy at 32 regs), loop keeps load pipe primed across iterations.

#define B_  32
#define H_  256
#define W_  256
#define C_  128
#define HO_ (H_ / 2)
#define WO_ (W_ / 2)
#define C4_ (C_ / 4)                    // 32 float4 per pixel
#define ROW4_ (W_ * C_ / 4)             // 8192 float4 per input row
#define TOTAL4_ (B_ * HO_ * WO_ * C4_)  // 16,777,216

#define NBLOCKS_ (152 * 4)              // GB300 has 152 SMs; 4 CTAs/SM resident
#define NTHREADS_ 512
#define STRIDE_ (NBLOCKS_ * NTHREADS_)  // 311,296

__global__ __launch_bounds__(NTHREADS_) void mixed_pool_kernel(
    const float4* __restrict__ x,
    const int4*   __restrict__ k,
    float4*       __restrict__ out)
{
    int tid = blockIdx.x * NTHREADS_ + threadIdx.x;

    for (int idx = tid; idx < TOTAL4_; idx += STRIDE_) {
        // idx -> (b, ho, wo, c4); C4_=32 (5b), WO_=128 (7b), HO_=128 (7b)
        int c4  = idx & (C4_ - 1);
        int wo  = (idx >> 5) & (WO_ - 1);
        int bho = idx >> 12;             // b*HO_ + ho

        int base = (bho * 2 * W_ + 2 * wo) * C4_ + c4;

        float4 p00 = x[base];
        float4 p01 = x[base + C4_];
        float4 p10 = x[base + ROW4_];
        float4 p11 = x[base + ROW4_ + C4_];
        int4   kv  = k[idx];

        float4 r;
        {
            float mx = fmaxf(fmaxf(p00.x, p01.x), fmaxf(p10.x, p11.x));
            float mn = (p00.x + p01.x + p10.x + p11.x) * 0.25f;
            r.x = fmaf((float)kv.x, mn - mx, mx);
        }
        {
            float mx = fmaxf(fmaxf(p00.y, p01.y), fmaxf(p10.y, p11.y));
            float mn = (p00.y + p01.y + p10.y + p11.y) * 0.25f;
            r.y = fmaf((float)kv.y, mn - mx, mx);
        }
        {
            float mx = fmaxf(fmaxf(p00.z, p01.z), fmaxf(p10.z, p11.z));
            float mn = (p00.z + p01.z + p10.z + p11.z) * 0.25f;
            r.z = fmaf((float)kv.z, mn - mx, mx);
        }
        {
            float mx = fmaxf(fmaxf(p00.w, p01.w), fmaxf(p10.w, p11.w));
            float mn = (p00.w + p01.w + p10.w + p11.w) * 0.25f;
            r.w = fmaf((float)kv.w, mn - mx, mx);
        }

        out[idx] = r;
    }
}

extern "C" void kernel_launch(void* const* d_in, const int* in_sizes, int n_in,
                              void* d_out, int out_size)
{
    const float4* x = (const float4*)d_in[0];
    const int4*   k = (const int4*)d_in[1];
    float4*       o = (float4*)d_out;

    mixed_pool_kernel<<<NBLOCKS_, NTHREADS_>>>(x, k, o);
}

// round 6
// speedup vs baseline: 1.0621x; 1.0621x over previous
#include <cuda_runtime.h>
#include <cuda_bf16.h>

// Mixed pooling, 2x2 stride-2, NHWC:
//   out[b,ho,wo,c] = (1-k)*max(window) + k*mean(window)
// x: [32,256,256,128] f32, k: [32,128,128,128] i32, out: [32,128,128,128] f32
//
// HBM-bound streaming kernel; traffic minimal (1.61 GB), riding DRAM ceiling.
// R6 = R4 memory pattern (1 float4 group/thread, default cache policy) with
// 1024-thread blocks (2 CTAs/SM, full occupancy) to minimize CTA transitions.

#define B_  32
#define H_  256
#define W_  256
#define C_  128
#define HO_ (H_ / 2)
#define WO_ (W_ / 2)
#define C4_ (C_ / 4)                    // 32 float4 per pixel
#define ROW4_ (W_ * C_ / 4)             // 8192 float4 per input row
#define TOTAL4_ (B_ * HO_ * WO_ * C4_)  // 16,777,216

__global__ __launch_bounds__(1024) void mixed_pool_kernel(
    const float4* __restrict__ x,
    const int4*   __restrict__ k,
    float4*       __restrict__ out)
{
    int idx = blockIdx.x * blockDim.x + threadIdx.x;

    // idx -> (b, ho, wo, c4); C4_=32 (5 bits), WO_=128 (7 bits), HO_=128 (7 bits)
    int c4  = idx & (C4_ - 1);
    int wo  = (idx >> 5) & (WO_ - 1);
    int bho = idx >> 12;                 // b*HO_ + ho

    // input base in float4 units: ((bho*2)*W + 2*wo)*C4 + c4
    int base = (bho * 2 * W_ + 2 * wo) * C4_ + c4;

    float4 p00 = x[base];
    float4 p01 = x[base + C4_];          // next column (wo*2+1)
    float4 p10 = x[base + ROW4_];        // next row (ho*2+1)
    float4 p11 = x[base + ROW4_ + C4_];
    int4   kv  = k[idx];

    float4 r;
    {
        float mx = fmaxf(fmaxf(p00.x, p01.x), fmaxf(p10.x, p11.x));
        float mn = (p00.x + p01.x + p10.x + p11.x) * 0.25f;
        r.x = fmaf((float)kv.x, mn - mx, mx);
    }
    {
        float mx = fmaxf(fmaxf(p00.y, p01.y), fmaxf(p10.y, p11.y));
        float mn = (p00.y + p01.y + p10.y + p11.y) * 0.25f;
        r.y = fmaf((float)kv.y, mn - mx, mx);
    }
    {
        float mx = fmaxf(fmaxf(p00.z, p01.z), fmaxf(p10.z, p11.z));
        float mn = (p00.z + p01.z + p10.z + p11.z) * 0.25f;
        r.z = fmaf((float)kv.z, mn - mx, mx);
    }
    {
        float mx = fmaxf(fmaxf(p00.w, p01.w), fmaxf(p10.w, p11.w));
        float mn = (p00.w + p01.w + p10.w + p11.w) * 0.25f;
        r.w = fmaf((float)kv.w, mn - mx, mx);
    }

    out[idx] = r;
}

extern "C" void kernel_launch(void* const* d_in, const int* in_sizes, int n_in,
                              void* d_out, int out_size)
{
    const float4* x = (const float4*)d_in[0];
    const int4*   k = (const int4*)d_in[1];
    float4*       o = (float4*)d_out;

    const int threads = 1024;
    const int blocks  = TOTAL4_ / threads;   // 16384
    mixed_pool_kernel<<<blocks, threads>>>(x, k, o);
}